// round 6
// baseline (speedup 1.0000x reference)
#include <cuda_runtime.h>

#define NGRAPH 256
#define M      512
#define KNN    6
#define C      32
#define NWARP  16          // 512 threads in main kernel
#define FINF   3.402823466e38f

typedef unsigned long long ull;

// inter-phase 'a' scratch + knn index scratch (L2-resident). Allocation-free.
__device__ float g_A[NGRAPH * M * C];
__device__ int   g_idx[NGRAPH * M * 8];

struct __align__(16) SmemLayout {
    float U[M * C];          // 64KB
    int   idxb[M * 8];       // 16KB byte-scaled neighbor offsets (idx*128), 6 used
    float hb[NWARP][2][C];   //  4KB per-warp h staging
    float red[NWARP * C];    //  2KB
};                           // ~86KB -> 2 CTAs/SM

static __device__ __forceinline__ ull pk2(float lo, float hi) {
    ull d; asm("mov.b64 %0, {%1, %2};" : "=l"(d) : "f"(lo), "f"(hi)); return d;
}
static __device__ __forceinline__ float2 upk2(ull v) {
    float2 r; asm("mov.b64 {%0, %1}, %2;" : "=f"(r.x), "=f"(r.y) : "l"(v)); return r;
}
static __device__ __forceinline__ ull ffma2(ull a, ull b, ull c) {
    ull d; asm("fma.rn.f32x2 %0, %1, %2, %3;" : "=l"(d) : "l"(a), "l"(b), "l"(c)); return d;
}

__device__ __forceinline__ void kins(float (&bd)[KNN], int (&bi)[KNN],
                                     float xd, int xi)
{
#pragma unroll
    for (int k = 0; k < KNN; k++) {
        bool  p  = xd < bd[k];          // strict: stable (ties keep earlier j)
        float td = bd[k];
        int   ti = bi[k];
        bd[k] = p ? xd : bd[k];
        bi[k] = p ? xi : bi[k];
        xd    = p ? td : xd;
        xi    = p ? ti : xi;
    }
}

// ============================================================================
// Kernel 1: brute-force KNN at high occupancy.
// 2 blocks per graph, 256 threads each; thread owns one node row.
// ============================================================================
__global__ void __launch_bounds__(256) knn_kernel(const float* __restrict__ pos)
{
    __shared__ float4 pos4s[M];       // 8KB
    const int b    = blockIdx.x >> 1;
    const int half = blockIdx.x & 1;
    const int tid  = threadIdx.x;

    // stage all 512 pos (+ |p|^2)
#pragma unroll
    for (int i = 0; i < 2; i++) {
        int n = i * 256 + tid;
        const float* p = pos + ((size_t)b * M + n) * 3;
        float px = p[0], py = p[1], pz = p[2];
        pos4s[n] = make_float4(px, py, pz, px * px + py * py + pz * pz);
    }
    __syncthreads();

    const int n = half * 256 + tid;
    float4 pn = pos4s[n];
    float bd[KNN];
    int   bi[KNN];
#pragma unroll
    for (int k = 0; k < KNN; k++) { bd[k] = FINF; bi[k] = 0; }
#pragma unroll 2
    for (int j = 0; j < M; j += 2) {
        float4 pa = pos4s[j];
        float4 pb = pos4s[j + 1];
        float dota = fmaf(pn.x, pa.x, fmaf(pn.y, pa.y, pn.z * pa.z));
        float dotb = fmaf(pn.x, pb.x, fmaf(pn.y, pb.y, pn.z * pb.z));
        float d2a  = fmaf(-2.0f, dota, pn.w + pa.w);
        float d2b  = fmaf(-2.0f, dotb, pn.w + pb.w);
        if (d2a < bd[KNN - 1]) kins(bd, bi, d2a, j);
        if (d2b < bd[KNN - 1]) kins(bd, bi, d2b, j + 1);
    }
    int* dst = g_idx + (size_t)b * M * 8 + n * 8;
    int4 v0 = make_int4(bi[0] << 7, bi[1] << 7, bi[2] << 7, bi[3] << 7);
    int4 v1 = make_int4(bi[4] << 7, bi[5] << 7, 0, 0);
    *(int4*)(dst)     = v0;
    *(int4*)(dst + 4) = v1;
}

// ============================================================================
// Kernel 2: fused 3-layer GCN + pool + head. One CTA per graph.
// ============================================================================
__global__ void __launch_bounds__(512, 2) gcn_layers_kernel(
    const float* __restrict__ x,   const float* __restrict__ pos,
    const float* __restrict__ W1a, const float* __restrict__ b1a,
    const float* __restrict__ W2a, const float* __restrict__ b2a,
    const float* __restrict__ W1b, const float* __restrict__ b1b,
    const float* __restrict__ W2b, const float* __restrict__ b2b,
    const float* __restrict__ W1c, const float* __restrict__ b1c,
    const float* __restrict__ W2c, const float* __restrict__ b2c,
    const float* __restrict__ Wr,  const float* __restrict__ brr,
    float* __restrict__ out)
{
    extern __shared__ char smem_raw[];
    SmemLayout& sm = *reinterpret_cast<SmemLayout*>(smem_raw);

    const int b    = blockIdx.x;
    const int tid  = threadIdx.x;
    const int lane = tid & 31;
    const int wid  = tid >> 5;
    const int base = wid * 32;

    float* __restrict__ Ag = g_A + (size_t)b * M * C;

    // ---- stage knn byte-offsets ----
    {
        const int4* src = (const int4*)(g_idx + (size_t)b * M * 8);
        int4* dst = (int4*)sm.idxb;
        dst[tid]       = src[tid];
        dst[tid + 512] = src[tid + 512];
    }

    float* hb0 = &sm.hb[wid][0][0];
    float* hb1 = &sm.hb[wid][1][0];

    // ---------- ph2 (all layers): u = W2·A(own rows) + b2 -> U (in place)
    auto ph2 = [&](const float* __restrict__ W2, const float* __restrict__ B2) {
        ull wp[16];
#pragma unroll
        for (int t = 0; t < 16; t++) {
            float2 wv = ((const float2*)W2)[lane * 16 + t];
            wp[t] = pk2(wv.x, wv.y);
        }
        float bb = B2[lane];
#pragma unroll 1
        for (int t = 0; t < 16; t++) {
            int n0 = base + 2 * t, n1 = n0 + 1;
            const ulonglong2* r0 = (const ulonglong2*)(Ag + n0 * C);
            const ulonglong2* r1 = (const ulonglong2*)(Ag + n1 * C);
            ull a00 = 0, a01 = 0, a10 = 0, a11 = 0;
#pragma unroll
            for (int q = 0; q < 8; q++) {
                ulonglong2 v0 = r0[q], v1 = r1[q];
                a00 = ffma2(wp[2*q], v0.x, a00); a01 = ffma2(wp[2*q+1], v0.y, a01);
                a10 = ffma2(wp[2*q], v1.x, a10); a11 = ffma2(wp[2*q+1], v1.y, a11);
            }
            float2 e0 = upk2(a00), e1 = upk2(a01);
            float2 e2 = upk2(a10), e3 = upk2(a11);
            sm.U[n0 * C + lane] = bb + ((e0.x + e0.y) + (e1.x + e1.y));
            sm.U[n1 * C + lane] = bb + ((e2.x + e2.y) + (e3.x + e3.y));
        }
    };

    // ========= layer A ph1: a = relu(W1a·[x,pos]+b1a) -> Ag (global pos reads) ====
    {
        float w10 = W1a[lane * 4 + 0], w11 = W1a[lane * 4 + 1];
        float w12 = W1a[lane * 4 + 2], w13 = W1a[lane * 4 + 3];
        float bb1 = b1a[lane];
        const float* pb = pos + (size_t)b * M * 3;
        const float* xb = x + (size_t)b * M;
#pragma unroll 1
        for (int t = 0; t < 16; t++) {
            int n0 = base + 2 * t, n1 = n0 + 1;
            float p0x = pb[n0*3], p0y = pb[n0*3+1], p0z = pb[n0*3+2];
            float p1x = pb[n1*3], p1y = pb[n1*3+1], p1z = pb[n1*3+2];
            float x0 = xb[n0], x1 = xb[n1];
            float a0 = fmaf(w10, x0, fmaf(w11, p0x, fmaf(w12, p0y, fmaf(w13, p0z, bb1))));
            float a1 = fmaf(w10, x1, fmaf(w11, p1x, fmaf(w12, p1y, fmaf(w13, p1z, bb1))));
            Ag[n0 * C + lane] = fmaxf(a0, 0.0f);
            Ag[n1 * C + lane] = fmaxf(a1, 0.0f);
        }
    }
    // no barrier: ph2 reads only own-warp Ag rows
    ph2(W2a, b2a);
    __syncthreads();   // U complete + idxb staged before gathers

    // ===================== layers B, C =====================
    auto ph1_32 = [&](const float* __restrict__ W1, const float* __restrict__ B1) {
        ull wp[16];
#pragma unroll
        for (int t = 0; t < 16; t++) {
            float2 wv = ((const float2*)W1)[lane * 16 + t];
            wp[t] = pk2(wv.x, wv.y);
        }
        float bb = B1[lane];
        const char* Ub = (const char*)sm.U + lane * 4;
#pragma unroll 1
        for (int t = 0; t < 16; t++) {
            int n0 = base + 2 * t, n1 = n0 + 1;
            const int4 ia0 = *(const int4*)&sm.idxb[n0 * 8];
            const int2 ib0 = *(const int2*)&sm.idxb[n0 * 8 + 4];
            const int4 ia1 = *(const int4*)&sm.idxb[n1 * 8];
            const int2 ib1 = *(const int2*)&sm.idxb[n1 * 8 + 4];
            float m0 =            *(const float*)(Ub + ia0.x);
            m0 = fmaxf(m0, *(const float*)(Ub + ia0.y));
            m0 = fmaxf(m0, *(const float*)(Ub + ia0.z));
            m0 = fmaxf(m0, *(const float*)(Ub + ia0.w));
            m0 = fmaxf(m0, *(const float*)(Ub + ib0.x));
            m0 = fmaxf(m0, *(const float*)(Ub + ib0.y));
            float m1 =            *(const float*)(Ub + ia1.x);
            m1 = fmaxf(m1, *(const float*)(Ub + ia1.y));
            m1 = fmaxf(m1, *(const float*)(Ub + ia1.z));
            m1 = fmaxf(m1, *(const float*)(Ub + ia1.w));
            m1 = fmaxf(m1, *(const float*)(Ub + ib1.x));
            m1 = fmaxf(m1, *(const float*)(Ub + ib1.y));
            hb0[lane] = fmaxf(m0, 0.0f);
            hb1[lane] = fmaxf(m1, 0.0f);
            __syncwarp();
            const ulonglong2* h0 = (const ulonglong2*)hb0;
            const ulonglong2* h1 = (const ulonglong2*)hb1;
            ull a00 = 0, a01 = 0, a10 = 0, a11 = 0;
#pragma unroll
            for (int q = 0; q < 8; q++) {
                ulonglong2 v0 = h0[q], v1 = h1[q];
                a00 = ffma2(wp[2*q], v0.x, a00); a01 = ffma2(wp[2*q+1], v0.y, a01);
                a10 = ffma2(wp[2*q], v1.x, a10); a11 = ffma2(wp[2*q+1], v1.y, a11);
            }
            float2 e0 = upk2(a00), e1 = upk2(a01);
            float2 e2 = upk2(a10), e3 = upk2(a11);
            Ag[n0 * C + lane] = fmaxf(bb + ((e0.x + e0.y) + (e1.x + e1.y)), 0.0f);
            Ag[n1 * C + lane] = fmaxf(bb + ((e2.x + e2.y) + (e3.x + e3.y)), 0.0f);
            __syncwarp();
        }
    };

    ph1_32(W1b, b1b);
    __syncthreads();   // all gathers from U done before ph2 overwrites U
    ph2(W2b, b2b);
    __syncthreads();

    ph1_32(W1c, b1c);
    __syncthreads();
    ph2(W2c, b2c);
    __syncthreads();

    // ============ final gather + relu + global max pool ============
    {
        const char* Ub = (const char*)sm.U + lane * 4;
        float g = -FINF;
#pragma unroll 1
        for (int t = 0; t < 32; t++) {
            int n = base + t;
            const int4 ia = *(const int4*)&sm.idxb[n * 8];
            const int2 ib = *(const int2*)&sm.idxb[n * 8 + 4];
            float m =            *(const float*)(Ub + ia.x);
            m = fmaxf(m, *(const float*)(Ub + ia.y));
            m = fmaxf(m, *(const float*)(Ub + ia.z));
            m = fmaxf(m, *(const float*)(Ub + ia.w));
            m = fmaxf(m, *(const float*)(Ub + ib.x));
            m = fmaxf(m, *(const float*)(Ub + ib.y));
            g = fmaxf(g, fmaxf(m, 0.0f));     // relu then pool
        }
        sm.red[wid * C + lane] = g;
    }
    __syncthreads();

    if (wid == 0) {
        float gg = sm.red[lane];
#pragma unroll
        for (int w = 1; w < NWARP; w++)
            gg = fmaxf(gg, sm.red[w * C + lane]);
#pragma unroll
        for (int od = 0; od < 6; od++) {
            float p = Wr[od * C + lane] * gg;
#pragma unroll
            for (int off = 16; off > 0; off >>= 1)
                p += __shfl_xor_sync(0xffffffffu, p, off);
            if (lane == 0) out[b * 6 + od] = p + brr[od];
        }
    }
}

extern "C" void kernel_launch(void* const* d_in, const int* in_sizes, int n_in,
                              void* d_out, int out_size)
{
    const float* x   = (const float*)d_in[0];
    const float* pos = (const float*)d_in[1];
    // d_in[2] = batch (int64), implicit in layout
    const float* W1a = (const float*)d_in[3];
    const float* b1a = (const float*)d_in[4];
    const float* W2a = (const float*)d_in[5];
    const float* b2a = (const float*)d_in[6];
    const float* W1b = (const float*)d_in[7];
    const float* b1b = (const float*)d_in[8];
    const float* W2b = (const float*)d_in[9];
    const float* b2b = (const float*)d_in[10];
    const float* W1c = (const float*)d_in[11];
    const float* b1c = (const float*)d_in[12];
    const float* W2c = (const float*)d_in[13];
    const float* b2c = (const float*)d_in[14];
    const float* Wr  = (const float*)d_in[15];
    const float* brr = (const float*)d_in[16];
    float* out = (float*)d_out;

    knn_kernel<<<NGRAPH * 2, 256>>>(pos);

    const size_t smem = sizeof(SmemLayout);
    cudaFuncSetAttribute(gcn_layers_kernel,
                         cudaFuncAttributeMaxDynamicSharedMemorySize, (int)smem);
    gcn_layers_kernel<<<NGRAPH, 512, smem>>>(
        x, pos,
        W1a, b1a, W2a, b2a,
        W1b, b1b, W2b, b2b,
        W1c, b1c, W2c, b2c,
        Wr, brr, out);
}